// round 7
// baseline (speedup 1.0000x reference)
#include <cuda_runtime.h>
#include <math.h>
#include <cstdint>

// Problem constants (fixed by reference: B=32, T=8192, K=16)
#define BT_ROWS   (32 * 8192)            // 262144 rows
#define KDIM      16
#define ELEMS     (BT_ROWS * KDIM)       // 4194304
#define NBLK      2048
#define NTHR      256                    // 524288 threads x 8 elems = ELEMS exactly
#define EPS_F     1e-7f
#define FULLMASK  0xffffffffu

// Per-block partial sums: [6][NBLK]
// j=0 fire_bce, j=1 live_count, j=2 valid_bce, j=3 cancel_ce, j=4 has_count, j=5 write_bce
__device__ float g_part[6 * NBLK];
__device__ unsigned int g_sem;   // zero-initialized; reset by last block each launch

__device__ __forceinline__ float warp_sum_f(float v) {
#pragma unroll
    for (int o = 16; o > 0; o >>= 1)
        v += __shfl_down_sync(FULLMASK, v, o);
    return v;
}
__device__ __forceinline__ double warp_sum_d(double v) {
#pragma unroll
    for (int o = 16; o > 0; o >>= 1)
        v += __shfl_down_sync(FULLMASK, v, o);
    return v;
}

__global__ __launch_bounds__(NTHR, 3)
void lifecycle_fused(const float* __restrict__ trig,          // (B,T,K)
                     const float* __restrict__ vld,           // (B,T,K)
                     const float* __restrict__ clog,          // (B,T,K,3)
                     const float* __restrict__ wsc,           // (B,T,1)
                     const void*  __restrict__ live_raw,      // (B,T,K) bool, dtype sniffed
                     const int*   __restrict__ cid,           // (B,T,K)
                     const float* __restrict__ ofire,         // (B,T,K)
                     const int*   __restrict__ ocan,          // (B,T,K)
                     const float* __restrict__ ovld,          // (B,T,K)
                     const float* __restrict__ osw,           // (B,T,1)
                     const int*   __restrict__ ocid,          // (B,T,K)
                     float* __restrict__ out)                 // (5,)
{
    // ---- Inline live_mask dtype sniff (all blocks read same 64 words; L2 broadcast) ----
    // mode 0 = uint8 bytes, 1 = int32 words, 2 = float32 words
    __shared__ unsigned int s_or, s_f32;
    __shared__ int s_mode;
    if (threadIdx.x == 0) { s_or = 0u; s_f32 = 0u; }
    __syncthreads();
    if (threadIdx.x < 64) {
        unsigned int x = ((const unsigned int*)live_raw)[threadIdx.x];
        unsigned int f = (x == 0x3F800000u) ? 1u : 0u;
        unsigned int a = f ? 0u : x;
#pragma unroll
        for (int o = 16; o > 0; o >>= 1) {
            a |= __shfl_down_sync(FULLMASK, a, o);
            f |= __shfl_down_sync(FULLMASK, f, o);
        }
        if ((threadIdx.x & 31) == 0) { atomicOr(&s_or, a); atomicOr(&s_f32, f); }
    }
    __syncthreads();
    if (threadIdx.x == 0)
        s_mode = s_f32 ? 2 : ((s_or & ~1u) ? 0 : 1);
    __syncthreads();
    const int mode = s_mode;

    const int e0     = (blockIdx.x * NTHR + threadIdx.x) << 3;  // first of my 8 elements
    const int rowe   = e0 & ~15;                                 // row base element
    const int parity = (e0 >> 3) & 1;                            // 0: ko 0..7, 1: ko 8..15

    // ---- Issue ALL DRAM traffic up front (independent 128-bit loads) ----
    const int g4 = e0 >> 2;  // float4/int4 group index (2 per thread)
    const int4   c0 = ((const int4*)cid)[g4],    c1 = ((const int4*)cid)[g4 + 1];
    const int4   o0 = ((const int4*)ocid)[g4],   o1 = ((const int4*)ocid)[g4 + 1];
    const float4 t0 = ((const float4*)trig)[g4], t1 = ((const float4*)trig)[g4 + 1];
    const float4 v0 = ((const float4*)vld)[g4],  v1 = ((const float4*)vld)[g4 + 1];

    // Prefetch target-array lines (gathers later hit L1, no dependent DRAM trip)
    asm volatile("prefetch.global.L1 [%0];" :: "l"(ofire + e0));
    asm volatile("prefetch.global.L1 [%0];" :: "l"(ovld  + e0));
    asm volatile("prefetch.global.L1 [%0];" :: "l"(ocan  + e0));

    // live -> 8-bit mask (dtype-aware, uniform branch)
    unsigned int lmask = 0u;
    if (mode == 0) {
        uint2 L = *(const uint2*)((const unsigned char*)live_raw + e0);
        unsigned int w[2] = {L.x, L.y};
#pragma unroll
        for (int i = 0; i < 8; ++i)
            if ((w[i >> 2] >> (8 * (i & 3))) & 0xFFu) lmask |= (1u << i);
    } else if (mode == 1) {
        int4 a = ((const int4*)live_raw)[g4], b = ((const int4*)live_raw)[g4 + 1];
        if (a.x) lmask |= 1u;   if (a.y) lmask |= 2u;
        if (a.z) lmask |= 4u;   if (a.w) lmask |= 8u;
        if (b.x) lmask |= 16u;  if (b.y) lmask |= 32u;
        if (b.z) lmask |= 64u;  if (b.w) lmask |= 128u;
    } else {
        float4 a = ((const float4*)live_raw)[g4], b = ((const float4*)live_raw)[g4 + 1];
        if (a.x != 0.f) lmask |= 1u;   if (a.y != 0.f) lmask |= 2u;
        if (a.z != 0.f) lmask |= 4u;   if (a.w != 0.f) lmask |= 8u;
        if (b.x != 0.f) lmask |= 16u;  if (b.y != 0.f) lmask |= 32u;
        if (b.z != 0.f) lmask |= 64u;  if (b.w != 0.f) lmask |= 128u;
    }

    // ---- Build the full 16-entry row ocid table: own 8 + partner's 8 via shfl_xor ----
    int own[8] = {o0.x, o0.y, o0.z, o0.w, o1.x, o1.y, o1.z, o1.w};
    int par[8];
#pragma unroll
    for (int j = 0; j < 8; ++j)
        par[j] = __shfl_xor_sync(FULLMASK, own[j], 1, 32);
    int ov[16];
#pragma unroll
    for (int j = 0; j < 8; ++j) {
        ov[j]     = parity ? par[j] : own[j];
        ov[j + 8] = parity ? own[j] : par[j];
    }

    const int   carr[8]  = {c0.x, c0.y, c0.z, c0.w, c1.x, c1.y, c1.z, c1.w};
    const float tharr[8] = {t0.x, t0.y, t0.z, t0.w, t1.x, t1.y, t1.z, t1.w};
    const float vvarr[8] = {v0.x, v0.y, v0.z, v0.w, v1.x, v1.y, v1.z, v1.w};

    float fire_s = 0.f, m_s = 0.f, val_s = 0.f, can_s = 0.f, has_s = 0.f, w_s = 0.f;

#pragma unroll
    for (int i = 0; i < 8; ++i) {
        const int c = carr[i];
        // first match = smallest ko (descending scan so the last write wins)
        int idx = 16;
#pragma unroll
        for (int ko = 15; ko >= 0; --ko)
            if (ov[ko] == c) idx = ko;
        const bool fnd  = (idx < 16) && (c != 0);
        const int  gidx = rowe + (fnd ? idx : 0);

        if ((lmask >> i) & 1u) {
            m_s += 1.0f;

            // L1-hit gathers (lines prefetched above by this thread pair)
            const float tf = fnd ? __ldg(&ofire[gidx]) : 0.0f;
            const float tv = fnd ? __ldg(&ovld[gidx])  : 0.0f;
            const int   ct = fnd ? __ldg(&ocan[gidx])  : 0;

            float p = fminf(fmaxf(tharr[i], EPS_F), 1.0f - EPS_F);
            fire_s -= tf * __logf(p) + (1.0f - tf) * __logf(1.0f - p);

            float q = fminf(fmaxf(vvarr[i], EPS_F), 1.0f - EPS_F);
            val_s -= tv * __logf(q) + (1.0f - tv) * __logf(1.0f - q);

            if (ct > 0) {
                const float* lp = clog + (size_t)(e0 + i) * 3;
                float x0 = lp[0], x1 = lp[1], x2 = lp[2];
                float mx = fmaxf(x0, fmaxf(x1, x2));
                float s  = __expf(x0 - mx) + __expf(x1 - mx) + __expf(x2 - mx);
                int tgt = ct - 1;
                tgt = tgt < 0 ? 0 : (tgt > 2 ? 2 : tgt);
                float xt = (tgt == 0) ? x0 : ((tgt == 1) ? x1 : x2);
                can_s += mx + __logf(s) - xt;
                has_s += 1.0f;
            }
        }
    }

    // write-head BCE-with-logits: one per row (parity-0 thread)
    if (parity == 0) {
        const int row = e0 >> 4;
        float wx = wsc[row], wy = osw[row];
        w_s = fmaxf(wx, 0.0f) - wx * wy + __logf(1.0f + __expf(-fabsf(wx)));
    }

    // ---- Deterministic block reduction of 6 float accumulators ----
    __shared__ float sm[8][6];
    {
        float vals[6] = {fire_s, m_s, val_s, can_s, has_s, w_s};
#pragma unroll
        for (int j = 0; j < 6; ++j) vals[j] = warp_sum_f(vals[j]);
        const int wid = threadIdx.x >> 5, lid = threadIdx.x & 31;
        if (lid == 0) {
#pragma unroll
            for (int j = 0; j < 6; ++j) sm[wid][j] = vals[j];
        }
        __syncthreads();
        if (wid == 0) {
#pragma unroll
            for (int j = 0; j < 6; ++j) {
                float v = (lid < (NTHR / 32)) ? sm[lid][j] : 0.0f;
                v = warp_sum_f(v);
                if (lid == 0) g_part[j * NBLK + blockIdx.x] = v;
            }
        }
    }

    // ---- Last-block finalize (threadfence reduction) ----
    __shared__ int s_last;
    if (threadIdx.x == 0) {
        __threadfence();
        unsigned int t = atomicAdd(&g_sem, 1u);
        s_last = (t == NBLK - 1) ? 1 : 0;
    }
    __syncthreads();
    if (!s_last) return;

    __shared__ double smd[8];
    double tot[6];
#pragma unroll
    for (int j = 0; j < 6; ++j) {
        double v = 0.0;
        for (int i = threadIdx.x; i < NBLK; i += NTHR)
            v += (double)__ldcg(&g_part[j * NBLK + i]);
        v = warp_sum_d(v);
        const int wid = threadIdx.x >> 5, lid = threadIdx.x & 31;
        if (lid == 0) smd[wid] = v;
        __syncthreads();
        double r = 0.0;
        if (wid == 0) {
            r = (lid < (NTHR / 32)) ? smd[lid] : 0.0;
            r = warp_sum_d(r);
        }
        tot[j] = r;  // valid on thread 0
        __syncthreads();
    }
    if (threadIdx.x == 0) {
        double n     = fmax(tot[1], 1.0);
        double fire  = tot[0] / n;                                        // LAM_FIRE   = 1.0
        double canc  = (tot[4] > 0.0) ? tot[3] / fmax(tot[4], 1.0) : 0.0; // LAM_CANCEL = 1.0
        double valid = 0.5 * tot[2] / n;                                  // LAM_VALID  = 0.5
        double wr    = 0.5 * tot[5] / (double)BT_ROWS;                    // LAM_WRITE  = 0.5
        out[0] = (float)fire;
        out[1] = (float)canc;
        out[2] = (float)valid;
        out[3] = (float)wr;
        out[4] = (float)(fire + canc + valid + wr);
        g_sem = 0;   // reset for next graph replay
    }
}

extern "C" void kernel_launch(void* const* d_in, const int* in_sizes, int n_in,
                              void* d_out, int out_size)
{
    (void)in_sizes; (void)n_in; (void)out_size;
    lifecycle_fused<<<NBLK, NTHR>>>(
        (const float*)d_in[0],          // trigger_hazard
        (const float*)d_in[1],          // validity
        (const float*)d_in[2],          // cancel_logits
        (const float*)d_in[3],          // write_score
        d_in[4],                        // live_mask (dtype auto-detected)
        (const int*)d_in[5],            // contract_id
        (const float*)d_in[6],          // oracle_fire
        (const int*)d_in[7],            // oracle_cancel
        (const float*)d_in[8],          // oracle_valid
        (const float*)d_in[9],          // oracle_should_write
        (const int*)d_in[10],           // oracle_contract_id
        (float*)d_out);
}

// round 8
// speedup vs baseline: 1.0733x; 1.0733x over previous
#include <cuda_runtime.h>
#include <math.h>
#include <cstdint>

// Problem constants (fixed by reference: B=32, T=8192, K=16)
#define BT_ROWS   (32 * 8192)            // 262144 rows
#define KDIM      16
#define ELEMS     (BT_ROWS * KDIM)       // 4194304
#define NBLK      2048
#define NTHR      256
#define NTHREADS  (NBLK * NTHR)          // 524288
#define ITER      (ELEMS / NTHREADS)     // 8, exact
#define EPS_F     1e-7f
#define FULLMASK  0xffffffffu

// Per-block partial sums: [6][NBLK]
// j=0 fire_bce, j=1 live_count, j=2 valid_bce, j=3 cancel_ce, j=4 has_count, j=5 write_bce
__device__ float g_part[6 * NBLK];
__device__ unsigned int g_sem;   // zero-initialized; reset by last block each launch

__device__ __forceinline__ float warp_sum_f(float v) {
#pragma unroll
    for (int o = 16; o > 0; o >>= 1)
        v += __shfl_down_sync(FULLMASK, v, o);
    return v;
}
__device__ __forceinline__ double warp_sum_d(double v) {
#pragma unroll
    for (int o = 16; o > 0; o >>= 1)
        v += __shfl_down_sync(FULLMASK, v, o);
    return v;
}

__global__ __launch_bounds__(NTHR)
void lifecycle_fused(const float* __restrict__ trig,          // (B,T,K)
                     const float* __restrict__ vld,           // (B,T,K)
                     const float* __restrict__ clog,          // (B,T,K,3)
                     const float* __restrict__ wsc,           // (B,T,1)
                     const void*  __restrict__ live_raw,      // (B,T,K) bool, dtype sniffed
                     const int*   __restrict__ cid,           // (B,T,K)
                     const float* __restrict__ ofire,         // (B,T,K)
                     const int*   __restrict__ ocan,          // (B,T,K)
                     const float* __restrict__ ovld,          // (B,T,K)
                     const float* __restrict__ osw,           // (B,T,1)
                     const int*   __restrict__ ocid,          // (B,T,K)
                     float* __restrict__ out)                 // (5,)
{
    // ---- Inline live_mask dtype sniff (all blocks read same 64 words; L2 broadcast) ----
    // mode 0 = uint8 bytes, 1 = int32 words, 2 = float32 words
    __shared__ unsigned int s_or, s_f32;
    __shared__ int s_mode;
    if (threadIdx.x == 0) { s_or = 0u; s_f32 = 0u; }
    __syncthreads();
    if (threadIdx.x < 64) {
        unsigned int x = ((const unsigned int*)live_raw)[threadIdx.x];
        unsigned int f = (x == 0x3F800000u) ? 1u : 0u;
        unsigned int a = f ? 0u : x;
#pragma unroll
        for (int o = 16; o > 0; o >>= 1) {
            a |= __shfl_down_sync(FULLMASK, a, o);
            f |= __shfl_down_sync(FULLMASK, f, o);
        }
        if ((threadIdx.x & 31) == 0) { atomicOr(&s_or, a); atomicOr(&s_f32, f); }
    }
    __syncthreads();
    if (threadIdx.x == 0)
        s_mode = s_f32 ? 2 : ((s_or & ~1u) ? 0 : 1);
    __syncthreads();
    const int mode = s_mode;

    const unsigned int lane  = threadIdx.x & 31;
    const unsigned int gbase = lane & ~15u;   // 16-lane row group base within warp

    float fire_s = 0.f, m_s = 0.f, val_s = 0.f, can_s = 0.f, has_s = 0.f, w_s = 0.f;

    int e = blockIdx.x * NTHR + threadIdx.x;  // element index; lane k = e & 15 (stable)
#pragma unroll
    for (int it = 0; it < ITER; ++it, e += NTHREADS) {
        const int row = e >> 4;
        const int k   = e & 15;

        // Coalesced per-element loads (compiler batches these across the loop)
        const int   c  = cid[e];
        const int   o  = ocid[e];
        const float th = trig[e];
        const float vv = vld[e];
        const float tf_own = ofire[e];
        const float tv_own = ovld[e];
        const int   ct_own = ocan[e];

        // live flag per detected dtype (uniform branch)
        bool lm;
        if (mode == 0)      lm = ((const unsigned char*)live_raw)[e] != 0;
        else if (mode == 1) lm = ((const int*)live_raw)[e] != 0;
        else                lm = ((const float*)live_raw)[e] != 0.0f;

        // First-match scan across the 16-lane group via shuffles
        int idx16 = 16;
#pragma unroll
        for (int ko = 15; ko >= 0; --ko) {
            int ov = __shfl_sync(FULLMASK, o, gbase + ko, 32);
            if (ov == c) idx16 = ko;
        }
        const bool fnd = (idx16 < 16) && (c != 0);
        const int  src = gbase + (fnd ? idx16 : 0);

        // Gather oracle targets via shuffle (lanes already hold them)
        float tf = __shfl_sync(FULLMASK, tf_own, src, 32);
        float tv = __shfl_sync(FULLMASK, tv_own, src, 32);
        int   ct = __shfl_sync(FULLMASK, ct_own, src, 32);
        if (!fnd) { tf = 0.f; tv = 0.f; ct = 0; }

        if (lm) {
            m_s += 1.0f;

            float p = fminf(fmaxf(th, EPS_F), 1.0f - EPS_F);
            fire_s -= tf * __logf(p) + (1.0f - tf) * __logf(1.0f - p);

            float q = fminf(fmaxf(vv, EPS_F), 1.0f - EPS_F);
            val_s -= tv * __logf(q) + (1.0f - tv) * __logf(1.0f - q);

            if (ct > 0) {
                const float* lp = clog + (size_t)e * 3;
                float x0 = lp[0], x1 = lp[1], x2 = lp[2];
                float mx = fmaxf(x0, fmaxf(x1, x2));
                float s  = __expf(x0 - mx) + __expf(x1 - mx) + __expf(x2 - mx);
                int tgt = ct - 1;                 // ocan in 0..3 -> tgt 0..2
                tgt = tgt < 0 ? 0 : (tgt > 2 ? 2 : tgt);
                float xt = (tgt == 0) ? x0 : ((tgt == 1) ? x1 : x2);
                can_s += mx + __logf(s) - xt;
                has_s += 1.0f;
            }
        }

        // write-head BCE-with-logits: one per row (lane with k==0)
        if (k == 0) {
            float wx = wsc[row], wy = osw[row];
            w_s += fmaxf(wx, 0.0f) - wx * wy + __logf(1.0f + __expf(-fabsf(wx)));
        }
    }

    // ---- Deterministic block reduction of 6 float accumulators ----
    __shared__ float sm[8][6];
    {
        float vals[6] = {fire_s, m_s, val_s, can_s, has_s, w_s};
#pragma unroll
        for (int j = 0; j < 6; ++j) vals[j] = warp_sum_f(vals[j]);
        const int wid = threadIdx.x >> 5, lid = threadIdx.x & 31;
        if (lid == 0) {
#pragma unroll
            for (int j = 0; j < 6; ++j) sm[wid][j] = vals[j];
        }
        __syncthreads();
        if (wid == 0) {
#pragma unroll
            for (int j = 0; j < 6; ++j) {
                float v = (lid < (NTHR / 32)) ? sm[lid][j] : 0.0f;
                v = warp_sum_f(v);
                if (lid == 0) g_part[j * NBLK + blockIdx.x] = v;
            }
        }
    }

    // ---- Last-block finalize (threadfence reduction) ----
    __shared__ int s_last;
    if (threadIdx.x == 0) {
        __threadfence();
        unsigned int t = atomicAdd(&g_sem, 1u);
        s_last = (t == NBLK - 1) ? 1 : 0;
    }
    __syncthreads();
    if (!s_last) return;

    __shared__ double smd[8];
    double tot[6];
#pragma unroll
    for (int j = 0; j < 6; ++j) {
        double v = 0.0;
        for (int i = threadIdx.x; i < NBLK; i += NTHR)
            v += (double)__ldcg(&g_part[j * NBLK + i]);
        v = warp_sum_d(v);
        const int wid = threadIdx.x >> 5, lid = threadIdx.x & 31;
        if (lid == 0) smd[wid] = v;
        __syncthreads();
        double r = 0.0;
        if (wid == 0) {
            r = (lid < (NTHR / 32)) ? smd[lid] : 0.0;
            r = warp_sum_d(r);
        }
        tot[j] = r;  // valid on thread 0
        __syncthreads();
    }
    if (threadIdx.x == 0) {
        double n     = fmax(tot[1], 1.0);
        double fire  = tot[0] / n;                                        // LAM_FIRE   = 1.0
        double canc  = (tot[4] > 0.0) ? tot[3] / fmax(tot[4], 1.0) : 0.0; // LAM_CANCEL = 1.0
        double valid = 0.5 * tot[2] / n;                                  // LAM_VALID  = 0.5
        double wr    = 0.5 * tot[5] / (double)BT_ROWS;                    // LAM_WRITE  = 0.5
        out[0] = (float)fire;
        out[1] = (float)canc;
        out[2] = (float)valid;
        out[3] = (float)wr;
        out[4] = (float)(fire + canc + valid + wr);
        g_sem = 0;   // reset for next graph replay
    }
}

extern "C" void kernel_launch(void* const* d_in, const int* in_sizes, int n_in,
                              void* d_out, int out_size)
{
    (void)in_sizes; (void)n_in; (void)out_size;
    lifecycle_fused<<<NBLK, NTHR>>>(
        (const float*)d_in[0],          // trigger_hazard
        (const float*)d_in[1],          // validity
        (const float*)d_in[2],          // cancel_logits
        (const float*)d_in[3],          // write_score
        d_in[4],                        // live_mask (dtype auto-detected)
        (const int*)d_in[5],            // contract_id
        (const float*)d_in[6],          // oracle_fire
        (const int*)d_in[7],            // oracle_cancel
        (const float*)d_in[8],          // oracle_valid
        (const float*)d_in[9],          // oracle_should_write
        (const int*)d_in[10],           // oracle_contract_id
        (float*)d_out);
}

// round 9
// speedup vs baseline: 1.2880x; 1.2000x over previous
#include <cuda_runtime.h>
#include <math.h>
#include <cstdint>

// Problem constants (fixed by reference: B=32, T=8192, K=16)
#define BT_ROWS   (32 * 8192)
#define KDIM      16
#define ELEMS     (BT_ROWS * KDIM)       // 4194304
#define NTHR      256
#define TILE      1024                   // elements per stage
#define NTILES    (ELEMS / TILE)         // 4096
#define NBLK      512
#define TPB       (NTILES / NBLK)        // 8 tiles per block, contiguous
#define EPS_F     1e-7f
#define FULLMASK  0xffffffffu

// ---- Stage layout in shared memory (bytes) ----
#define OFF_CID    0
#define OFF_OCID   (4*1024)
#define OFF_TRIG   (8*1024)
#define OFF_VLD    (12*1024)
#define OFF_OFIRE  (16*1024)
#define OFF_OVLD   (20*1024)
#define OFF_OCAN   (24*1024)
#define OFF_CLOG   (28*1024)             // 12 KB
#define OFF_LIVE   (40*1024)             // up to 4 KB
#define OFF_WSC    (44*1024)             // 256 B
#define OFF_OSW    (44*1024 + 256)       // 256 B
#define STAGE_BYTES (44*1024 + 512)      // 45568
#define SMEM_TOTAL  (2 * STAGE_BYTES)    // 91136

// Per-block partial sums: [6][NBLK]
__device__ float g_part[6 * NBLK];
__device__ unsigned int g_sem;

__device__ __forceinline__ float warp_sum_f(float v) {
#pragma unroll
    for (int o = 16; o > 0; o >>= 1) v += __shfl_down_sync(FULLMASK, v, o);
    return v;
}
__device__ __forceinline__ double warp_sum_d(double v) {
#pragma unroll
    for (int o = 16; o > 0; o >>= 1) v += __shfl_down_sync(FULLMASK, v, o);
    return v;
}

__device__ __forceinline__ void cpa16(uint32_t dst, const void* src) {
    asm volatile("cp.async.cg.shared.global [%0], [%1], 16;\n" :: "r"(dst), "l"(src));
}
__device__ __forceinline__ void cpa_commit() {
    asm volatile("cp.async.commit_group;\n" ::: "memory");
}
__device__ __forceinline__ void cpa_wait1() {
    asm volatile("cp.async.wait_group 1;\n" ::: "memory");
}
__device__ __forceinline__ void cpa_wait0() {
    asm volatile("cp.async.wait_group 0;\n" ::: "memory");
}

__global__ __launch_bounds__(NTHR)
void lifecycle_fused(const float* __restrict__ trig,
                     const float* __restrict__ vld,
                     const float* __restrict__ clog,
                     const float* __restrict__ wsc,
                     const void*  __restrict__ live_raw,
                     const int*   __restrict__ cid,
                     const float* __restrict__ ofire,
                     const int*   __restrict__ ocan,
                     const float* __restrict__ ovld,
                     const float* __restrict__ osw,
                     const int*   __restrict__ ocid,
                     float* __restrict__ out)
{
    extern __shared__ char smem[];

    // ---- live_mask dtype sniff (same 64 words for every block; L2 broadcast) ----
    __shared__ unsigned int s_or, s_f32;
    __shared__ int s_mode;
    if (threadIdx.x == 0) { s_or = 0u; s_f32 = 0u; }
    __syncthreads();
    if (threadIdx.x < 64) {
        unsigned int x = ((const unsigned int*)live_raw)[threadIdx.x];
        unsigned int f = (x == 0x3F800000u) ? 1u : 0u;
        unsigned int a = f ? 0u : x;
#pragma unroll
        for (int o = 16; o > 0; o >>= 1) {
            a |= __shfl_down_sync(FULLMASK, a, o);
            f |= __shfl_down_sync(FULLMASK, f, o);
        }
        if ((threadIdx.x & 31) == 0) { atomicOr(&s_or, a); atomicOr(&s_f32, f); }
    }
    __syncthreads();
    if (threadIdx.x == 0) s_mode = s_f32 ? 2 : ((s_or & ~1u) ? 0 : 1);
    __syncthreads();
    const int mode = s_mode;                    // 0=u8, 1=i32, 2=f32
    const int lesz = (mode == 0) ? 1 : 4;       // live element size

    const int tid = threadIdx.x;

    // ---- tile stage: issue cp.async for every array, one commit group ----
    auto stage_copy = [&](int j, int buf) {
        const int tt = blockIdx.x * TPB + j;
        const size_t eb = (size_t)tt * TILE;
        uint32_t sb = (uint32_t)__cvta_generic_to_shared(smem + buf * STAGE_BYTES);
        // 7 x 4KB arrays: exactly 1 chunk per thread each
        cpa16(sb + OFF_CID   + tid*16, (const char*)cid   + eb*4  + tid*16);
        cpa16(sb + OFF_OCID  + tid*16, (const char*)ocid  + eb*4  + tid*16);
        cpa16(sb + OFF_TRIG  + tid*16, (const char*)trig  + eb*4  + tid*16);
        cpa16(sb + OFF_VLD   + tid*16, (const char*)vld   + eb*4  + tid*16);
        cpa16(sb + OFF_OFIRE + tid*16, (const char*)ofire + eb*4  + tid*16);
        cpa16(sb + OFF_OVLD  + tid*16, (const char*)ovld  + eb*4  + tid*16);
        cpa16(sb + OFF_OCAN  + tid*16, (const char*)ocan  + eb*4  + tid*16);
        // clog: 12KB = 3 chunks per thread
#pragma unroll
        for (int i = 0; i < 3; ++i)
            cpa16(sb + OFF_CLOG + (tid + i*NTHR)*16, (const char*)clog + eb*12 + (tid + i*NTHR)*16);
        // live: 1KB (64 chunks) or 4KB (256 chunks)
        if (mode == 0) {
            if (tid < 64)
                cpa16(sb + OFF_LIVE + tid*16, (const char*)live_raw + eb + tid*16);
        } else {
            cpa16(sb + OFF_LIVE + tid*16, (const char*)live_raw + eb*4 + tid*16);
        }
        // wsc / osw: 256B each (16 chunks)
        if (tid < 16) {
            cpa16(sb + OFF_WSC + tid*16, (const char*)wsc + (eb >> 4)*4 + tid*16);
            cpa16(sb + OFF_OSW + tid*16, (const char*)osw + (eb >> 4)*4 + tid*16);
        }
        cpa_commit();
    };

    float fire_s = 0.f, m_s = 0.f, val_s = 0.f, can_s = 0.f, has_s = 0.f, w_s = 0.f;

    // ---- double-buffered pipeline over this block's 8 contiguous tiles ----
    stage_copy(0, 0);
#pragma unroll 1
    for (int j = 0; j < TPB; ++j) {
        if (j + 1 < TPB) { stage_copy(j + 1, (j + 1) & 1); cpa_wait1(); }
        else             { cpa_wait0(); }
        __syncthreads();

        const char* sb = smem + (j & 1) * STAGE_BYTES;
        const int le0 = tid * 4;            // 4 consecutive elements per thread
        const int row = le0 >> 4;           // local row (4 threads share a row)

        // 16-entry row ocid table: 4 conflict-free LDS.128
        int ov[16];
        {
            const int4* orow = (const int4*)(sb + OFF_OCID) + row * 4;
#pragma unroll
            for (int gq = 0; gq < 4; ++gq) {
                int4 t = orow[gq];
                ov[4*gq+0] = t.x; ov[4*gq+1] = t.y; ov[4*gq+2] = t.z; ov[4*gq+3] = t.w;
            }
        }

        const int4   c4 = ((const int4*)(sb + OFF_CID))[tid];
        const float4 t4 = ((const float4*)(sb + OFF_TRIG))[tid];
        const float4 v4 = ((const float4*)(sb + OFF_VLD))[tid];

        unsigned int lmask = 0u;
        if (mode == 0) {
            unsigned int w = *(const unsigned int*)(sb + OFF_LIVE + le0);
            if (w & 0x000000FFu) lmask |= 1u;
            if (w & 0x0000FF00u) lmask |= 2u;
            if (w & 0x00FF0000u) lmask |= 4u;
            if (w & 0xFF000000u) lmask |= 8u;
        } else if (mode == 1) {
            int4 L = ((const int4*)(sb + OFF_LIVE))[tid];
            if (L.x) lmask |= 1u; if (L.y) lmask |= 2u;
            if (L.z) lmask |= 4u; if (L.w) lmask |= 8u;
        } else {
            float4 L = ((const float4*)(sb + OFF_LIVE))[tid];
            if (L.x != 0.f) lmask |= 1u; if (L.y != 0.f) lmask |= 2u;
            if (L.z != 0.f) lmask |= 4u; if (L.w != 0.f) lmask |= 8u;
        }

        const float* s_ofire = (const float*)(sb + OFF_OFIRE);
        const float* s_ovld  = (const float*)(sb + OFF_OVLD);
        const int*   s_ocan  = (const int*)(sb + OFF_OCAN);
        const float* s_clog  = (const float*)(sb + OFF_CLOG);

        const int   carr[4]  = {c4.x, c4.y, c4.z, c4.w};
        const float tharr[4] = {t4.x, t4.y, t4.z, t4.w};
        const float vvarr[4] = {v4.x, v4.y, v4.z, v4.w};

#pragma unroll
        for (int i = 0; i < 4; ++i) {
            const int c = carr[i];
            int idx = 16;
#pragma unroll
            for (int ko = 15; ko >= 0; --ko)
                if (ov[ko] == c) idx = ko;             // first match wins
            const bool fnd = (idx < 16) && (c != 0);
            const int  gl  = row * 16 + (fnd ? idx : 0);

            if ((lmask >> i) & 1u) {
                m_s += 1.0f;

                const float tf = fnd ? s_ofire[gl] : 0.0f;
                const float tv = fnd ? s_ovld[gl]  : 0.0f;
                const int   ct = fnd ? s_ocan[gl]  : 0;

                float p = fminf(fmaxf(tharr[i], EPS_F), 1.0f - EPS_F);
                fire_s -= tf * __logf(p) + (1.0f - tf) * __logf(1.0f - p);

                float q = fminf(fmaxf(vvarr[i], EPS_F), 1.0f - EPS_F);
                val_s -= tv * __logf(q) + (1.0f - tv) * __logf(1.0f - q);

                if (ct > 0) {
                    const float* lp = s_clog + (size_t)(le0 + i) * 3;
                    float x0 = lp[0], x1 = lp[1], x2 = lp[2];
                    float mx = fmaxf(x0, fmaxf(x1, x2));
                    float s  = __expf(x0 - mx) + __expf(x1 - mx) + __expf(x2 - mx);
                    int tgt = ct - 1;
                    tgt = tgt < 0 ? 0 : (tgt > 2 ? 2 : tgt);
                    float xt = (tgt == 0) ? x0 : ((tgt == 1) ? x1 : x2);
                    can_s += mx + __logf(s) - xt;
                    has_s += 1.0f;
                }
            }
        }

        // write-head BCE-with-logits: one per row (thread with tid%4 == 0)
        if ((le0 & 15) == 0) {
            float wx = ((const float*)(sb + OFF_WSC))[row];
            float wy = ((const float*)(sb + OFF_OSW))[row];
            w_s += fmaxf(wx, 0.0f) - wx * wy + __logf(1.0f + __expf(-fabsf(wx)));
        }

        __syncthreads();   // buffer may be overwritten next iteration
    }

    // ---- Deterministic block reduction of 6 float accumulators ----
    __shared__ float sm[8][6];
    {
        float vals[6] = {fire_s, m_s, val_s, can_s, has_s, w_s};
#pragma unroll
        for (int jj = 0; jj < 6; ++jj) vals[jj] = warp_sum_f(vals[jj]);
        const int wid = tid >> 5, lid = tid & 31;
        if (lid == 0) {
#pragma unroll
            for (int jj = 0; jj < 6; ++jj) sm[wid][jj] = vals[jj];
        }
        __syncthreads();
        if (wid == 0) {
#pragma unroll
            for (int jj = 0; jj < 6; ++jj) {
                float v = (lid < (NTHR / 32)) ? sm[lid][jj] : 0.0f;
                v = warp_sum_f(v);
                if (lid == 0) g_part[jj * NBLK + blockIdx.x] = v;
            }
        }
    }

    // ---- Last-block finalize ----
    __shared__ int s_last;
    if (tid == 0) {
        __threadfence();
        unsigned int t = atomicAdd(&g_sem, 1u);
        s_last = (t == NBLK - 1) ? 1 : 0;
    }
    __syncthreads();
    if (!s_last) return;

    __shared__ double smd[8];
    double tot[6];
#pragma unroll
    for (int jj = 0; jj < 6; ++jj) {
        double v = 0.0;
        for (int i = tid; i < NBLK; i += NTHR)
            v += (double)__ldcg(&g_part[jj * NBLK + i]);
        v = warp_sum_d(v);
        const int wid = tid >> 5, lid = tid & 31;
        if (lid == 0) smd[wid] = v;
        __syncthreads();
        double r = 0.0;
        if (wid == 0) {
            r = (lid < (NTHR / 32)) ? smd[lid] : 0.0;
            r = warp_sum_d(r);
        }
        tot[jj] = r;
        __syncthreads();
    }
    if (tid == 0) {
        double n     = fmax(tot[1], 1.0);
        double fire  = tot[0] / n;
        double canc  = (tot[4] > 0.0) ? tot[3] / fmax(tot[4], 1.0) : 0.0;
        double valid = 0.5 * tot[2] / n;
        double wr    = 0.5 * tot[5] / (double)BT_ROWS;
        out[0] = (float)fire;
        out[1] = (float)canc;
        out[2] = (float)valid;
        out[3] = (float)wr;
        out[4] = (float)(fire + canc + valid + wr);
        g_sem = 0;
    }
}

extern "C" void kernel_launch(void* const* d_in, const int* in_sizes, int n_in,
                              void* d_out, int out_size)
{
    (void)in_sizes; (void)n_in; (void)out_size;
    cudaFuncSetAttribute(lifecycle_fused,
                         cudaFuncAttributeMaxDynamicSharedMemorySize, SMEM_TOTAL);
    lifecycle_fused<<<NBLK, NTHR, SMEM_TOTAL>>>(
        (const float*)d_in[0],          // trigger_hazard
        (const float*)d_in[1],          // validity
        (const float*)d_in[2],          // cancel_logits
        (const float*)d_in[3],          // write_score
        d_in[4],                        // live_mask (dtype auto-detected)
        (const int*)d_in[5],            // contract_id
        (const float*)d_in[6],          // oracle_fire
        (const int*)d_in[7],            // oracle_cancel
        (const float*)d_in[8],          // oracle_valid
        (const float*)d_in[9],          // oracle_should_write
        (const int*)d_in[10],           // oracle_contract_id
        (float*)d_out);
}

// round 10
// speedup vs baseline: 1.3258x; 1.0293x over previous
#include <cuda_runtime.h>
#include <math.h>
#include <cstdint>

// Problem constants (fixed by reference: B=32, T=8192, K=16)
#define BT_ROWS   (32 * 8192)
#define KDIM      16
#define ELEMS     (BT_ROWS * KDIM)       // 4194304
#define NTHR      512
#define TILE      1024                   // elements per stage
#define NTILES    (ELEMS / TILE)         // 4096
#define NBLK      512
#define TPB       (NTILES / NBLK)        // 8 tiles per block, contiguous
#define EPS_F     1e-7f
#define FULLMASK  0xffffffffu

// ---- Stage layout in shared memory (bytes) ----
#define OFF_CID    0
#define OFF_OCID   (4*1024)
#define OFF_TRIG   (8*1024)
#define OFF_VLD    (12*1024)
#define OFF_OFIRE  (16*1024)
#define OFF_OVLD   (20*1024)
#define OFF_OCAN   (24*1024)
#define OFF_CLOG   (28*1024)             // 12 KB
#define OFF_LIVE   (40*1024)             // up to 4 KB
#define OFF_WSC    (44*1024)             // 256 B
#define OFF_OSW    (44*1024 + 256)       // 256 B
#define STAGE_BYTES (44*1024 + 512)      // 45568
#define SMEM_TOTAL  (2 * STAGE_BYTES)    // 91136

// Per-block partial sums: [6][NBLK]
__device__ float g_part[6 * NBLK];
__device__ unsigned int g_sem;

__device__ __forceinline__ float warp_sum_f(float v) {
#pragma unroll
    for (int o = 16; o > 0; o >>= 1) v += __shfl_down_sync(FULLMASK, v, o);
    return v;
}
__device__ __forceinline__ double warp_sum_d(double v) {
#pragma unroll
    for (int o = 16; o > 0; o >>= 1) v += __shfl_down_sync(FULLMASK, v, o);
    return v;
}

__device__ __forceinline__ void cpa16(uint32_t dst, const void* src) {
    asm volatile("cp.async.cg.shared.global [%0], [%1], 16;\n" :: "r"(dst), "l"(src));
}
__device__ __forceinline__ void cpa_commit() {
    asm volatile("cp.async.commit_group;\n" ::: "memory");
}
__device__ __forceinline__ void cpa_wait1() {
    asm volatile("cp.async.wait_group 1;\n" ::: "memory");
}
__device__ __forceinline__ void cpa_wait0() {
    asm volatile("cp.async.wait_group 0;\n" ::: "memory");
}

__global__ __launch_bounds__(NTHR)
void lifecycle_fused(const float* __restrict__ trig,
                     const float* __restrict__ vld,
                     const float* __restrict__ clog,
                     const float* __restrict__ wsc,
                     const void*  __restrict__ live_raw,
                     const int*   __restrict__ cid,
                     const float* __restrict__ ofire,
                     const int*   __restrict__ ocan,
                     const float* __restrict__ ovld,
                     const float* __restrict__ osw,
                     const int*   __restrict__ ocid,
                     float* __restrict__ out)
{
    extern __shared__ char smem[];

    // ---- live_mask dtype sniff (same 64 words for every block; L2 broadcast) ----
    __shared__ unsigned int s_or, s_f32;
    __shared__ int s_mode;
    if (threadIdx.x == 0) { s_or = 0u; s_f32 = 0u; }
    __syncthreads();
    if (threadIdx.x < 64) {
        unsigned int x = ((const unsigned int*)live_raw)[threadIdx.x];
        unsigned int f = (x == 0x3F800000u) ? 1u : 0u;
        unsigned int a = f ? 0u : x;
#pragma unroll
        for (int o = 16; o > 0; o >>= 1) {
            a |= __shfl_down_sync(FULLMASK, a, o);
            f |= __shfl_down_sync(FULLMASK, f, o);
        }
        if ((threadIdx.x & 31) == 0) { atomicOr(&s_or, a); atomicOr(&s_f32, f); }
    }
    __syncthreads();
    if (threadIdx.x == 0) s_mode = s_f32 ? 2 : ((s_or & ~1u) ? 0 : 1);
    __syncthreads();
    const int mode = s_mode;                    // 0=u8, 1=i32, 2=f32

    const int tid = threadIdx.x;

    // ---- tile stage: issue cp.async for every array, one commit group ----
    auto stage_copy = [&](int j, int buf) {
        const int tt = blockIdx.x * TPB + j;
        const size_t eb = (size_t)tt * TILE;
        uint32_t sb = (uint32_t)__cvta_generic_to_shared(smem + buf * STAGE_BYTES);
        // 7 x 4KB arrays: 256 chunks each, staged by low 256 threads
        if (tid < 256) {
            cpa16(sb + OFF_CID   + tid*16, (const char*)cid   + eb*4 + tid*16);
            cpa16(sb + OFF_OCID  + tid*16, (const char*)ocid  + eb*4 + tid*16);
            cpa16(sb + OFF_TRIG  + tid*16, (const char*)trig  + eb*4 + tid*16);
            cpa16(sb + OFF_VLD   + tid*16, (const char*)vld   + eb*4 + tid*16);
            cpa16(sb + OFF_OFIRE + tid*16, (const char*)ofire + eb*4 + tid*16);
            cpa16(sb + OFF_OVLD  + tid*16, (const char*)ovld  + eb*4 + tid*16);
            cpa16(sb + OFF_OCAN  + tid*16, (const char*)ocan  + eb*4 + tid*16);
        }
        // clog: 12KB = 768 chunks: all 512 threads one chunk, low 256 a second
        cpa16(sb + OFF_CLOG + tid*16, (const char*)clog + eb*12 + tid*16);
        if (tid < 256)
            cpa16(sb + OFF_CLOG + (512 + tid)*16, (const char*)clog + eb*12 + (512 + tid)*16);
        // live: 1KB (64 chunks) or 4KB (256 chunks)
        if (mode == 0) {
            if (tid < 64)
                cpa16(sb + OFF_LIVE + tid*16, (const char*)live_raw + eb + tid*16);
        } else {
            if (tid < 256)
                cpa16(sb + OFF_LIVE + tid*16, (const char*)live_raw + eb*4 + tid*16);
        }
        // wsc / osw: 256B each (16 chunks)
        if (tid < 16) {
            cpa16(sb + OFF_WSC + tid*16, (const char*)wsc + (eb >> 4)*4 + tid*16);
            cpa16(sb + OFF_OSW + tid*16, (const char*)osw + (eb >> 4)*4 + tid*16);
        }
        cpa_commit();
    };

    float fire_s = 0.f, m_s = 0.f, val_s = 0.f, can_s = 0.f, has_s = 0.f, w_s = 0.f;

    // ---- double-buffered pipeline over this block's 8 contiguous tiles ----
    stage_copy(0, 0);
#pragma unroll 1
    for (int j = 0; j < TPB; ++j) {
        if (j + 1 < TPB) { stage_copy(j + 1, (j + 1) & 1); cpa_wait1(); }
        else             { cpa_wait0(); }
        __syncthreads();

        const char* sb = smem + (j & 1) * STAGE_BYTES;
        const int le0 = tid * 2;            // 2 consecutive elements per thread
        const int row = le0 >> 4;           // local row (8 threads share a row)

        // 16-entry row ocid table: 4 broadcast LDS.128
        int ov[16];
        {
            const int4* orow = (const int4*)(sb + OFF_OCID) + row * 4;
#pragma unroll
            for (int gq = 0; gq < 4; ++gq) {
                int4 t = orow[gq];
                ov[4*gq+0] = t.x; ov[4*gq+1] = t.y; ov[4*gq+2] = t.z; ov[4*gq+3] = t.w;
            }
        }

        const int2   c2 = ((const int2*)(sb + OFF_CID))[tid];
        const float2 t2 = ((const float2*)(sb + OFF_TRIG))[tid];
        const float2 v2 = ((const float2*)(sb + OFF_VLD))[tid];

        unsigned int lmask = 0u;
        if (mode == 0) {
            unsigned short w = *(const unsigned short*)(sb + OFF_LIVE + le0);
            if (w & 0x00FFu) lmask |= 1u;
            if (w & 0xFF00u) lmask |= 2u;
        } else if (mode == 1) {
            int2 L = ((const int2*)(sb + OFF_LIVE))[tid];
            if (L.x) lmask |= 1u; if (L.y) lmask |= 2u;
        } else {
            float2 L = ((const float2*)(sb + OFF_LIVE))[tid];
            if (L.x != 0.f) lmask |= 1u; if (L.y != 0.f) lmask |= 2u;
        }

        const float* s_ofire = (const float*)(sb + OFF_OFIRE);
        const float* s_ovld  = (const float*)(sb + OFF_OVLD);
        const int*   s_ocan  = (const int*)(sb + OFF_OCAN);
        const float* s_clog  = (const float*)(sb + OFF_CLOG);

        const int   carr[2]  = {c2.x, c2.y};
        const float tharr[2] = {t2.x, t2.y};
        const float vvarr[2] = {v2.x, v2.y};

#pragma unroll
        for (int i = 0; i < 2; ++i) {
            const int c = carr[i];
            int idx = 16;
#pragma unroll
            for (int ko = 15; ko >= 0; --ko)
                if (ov[ko] == c) idx = ko;             // first match wins
            const bool fnd = (idx < 16) && (c != 0);
            const int  gl  = row * 16 + (fnd ? idx : 0);

            if ((lmask >> i) & 1u) {
                m_s += 1.0f;

                const float tf = fnd ? s_ofire[gl] : 0.0f;
                const float tv = fnd ? s_ovld[gl]  : 0.0f;
                const int   ct = fnd ? s_ocan[gl]  : 0;

                float p = fminf(fmaxf(tharr[i], EPS_F), 1.0f - EPS_F);
                fire_s -= tf * __logf(p) + (1.0f - tf) * __logf(1.0f - p);

                float q = fminf(fmaxf(vvarr[i], EPS_F), 1.0f - EPS_F);
                val_s -= tv * __logf(q) + (1.0f - tv) * __logf(1.0f - q);

                if (ct > 0) {
                    const float* lp = s_clog + (size_t)(le0 + i) * 3;
                    float x0 = lp[0], x1 = lp[1], x2 = lp[2];
                    float mx = fmaxf(x0, fmaxf(x1, x2));
                    float s  = __expf(x0 - mx) + __expf(x1 - mx) + __expf(x2 - mx);
                    int tgt = ct - 1;
                    tgt = tgt < 0 ? 0 : (tgt > 2 ? 2 : tgt);
                    float xt = (tgt == 0) ? x0 : ((tgt == 1) ? x1 : x2);
                    can_s += mx + __logf(s) - xt;
                    has_s += 1.0f;
                }
            }
        }

        // write-head BCE-with-logits: one per row (thread with tid%8 == 0)
        if ((le0 & 15) == 0) {
            float wx = ((const float*)(sb + OFF_WSC))[row];
            float wy = ((const float*)(sb + OFF_OSW))[row];
            w_s += fmaxf(wx, 0.0f) - wx * wy + __logf(1.0f + __expf(-fabsf(wx)));
        }

        __syncthreads();   // buffer may be overwritten next iteration
    }

    // ---- Deterministic block reduction of 6 float accumulators ----
    __shared__ float sm[16][6];
    {
        float vals[6] = {fire_s, m_s, val_s, can_s, has_s, w_s};
#pragma unroll
        for (int jj = 0; jj < 6; ++jj) vals[jj] = warp_sum_f(vals[jj]);
        const int wid = tid >> 5, lid = tid & 31;
        if (lid == 0) {
#pragma unroll
            for (int jj = 0; jj < 6; ++jj) sm[wid][jj] = vals[jj];
        }
        __syncthreads();
        if (wid == 0) {
#pragma unroll
            for (int jj = 0; jj < 6; ++jj) {
                float v = (lid < (NTHR / 32)) ? sm[lid][jj] : 0.0f;
                v = warp_sum_f(v);
                if (lid == 0) g_part[jj * NBLK + blockIdx.x] = v;
            }
        }
    }

    // ---- Last-block finalize ----
    __shared__ int s_last;
    if (tid == 0) {
        __threadfence();
        unsigned int t = atomicAdd(&g_sem, 1u);
        s_last = (t == NBLK - 1) ? 1 : 0;
    }
    __syncthreads();
    if (!s_last) return;

    __shared__ double smd[16];
    double tot[6];
#pragma unroll
    for (int jj = 0; jj < 6; ++jj) {
        double v = 0.0;
        for (int i = tid; i < NBLK; i += NTHR)
            v += (double)__ldcg(&g_part[jj * NBLK + i]);
        v = warp_sum_d(v);
        const int wid = tid >> 5, lid = tid & 31;
        if (lid == 0) smd[wid] = v;
        __syncthreads();
        double r = 0.0;
        if (wid == 0) {
            r = (lid < (NTHR / 32)) ? smd[lid] : 0.0;
            r = warp_sum_d(r);
        }
        tot[jj] = r;
        __syncthreads();
    }
    if (tid == 0) {
        double n     = fmax(tot[1], 1.0);
        double fire  = tot[0] / n;
        double canc  = (tot[4] > 0.0) ? tot[3] / fmax(tot[4], 1.0) : 0.0;
        double valid = 0.5 * tot[2] / n;
        double wr    = 0.5 * tot[5] / (double)BT_ROWS;
        out[0] = (float)fire;
        out[1] = (float)canc;
        out[2] = (float)valid;
        out[3] = (float)wr;
        out[4] = (float)(fire + canc + valid + wr);
        g_sem = 0;
    }
}

extern "C" void kernel_launch(void* const* d_in, const int* in_sizes, int n_in,
                              void* d_out, int out_size)
{
    (void)in_sizes; (void)n_in; (void)out_size;
    cudaFuncSetAttribute(lifecycle_fused,
                         cudaFuncAttributeMaxDynamicSharedMemorySize, SMEM_TOTAL);
    lifecycle_fused<<<NBLK, NTHR, SMEM_TOTAL>>>(
        (const float*)d_in[0],          // trigger_hazard
        (const float*)d_in[1],          // validity
        (const float*)d_in[2],          // cancel_logits
        (const float*)d_in[3],          // write_score
        d_in[4],                        // live_mask (dtype auto-detected)
        (const int*)d_in[5],            // contract_id
        (const float*)d_in[6],          // oracle_fire
        (const int*)d_in[7],            // oracle_cancel
        (const float*)d_in[8],          // oracle_valid
        (const float*)d_in[9],          // oracle_should_write
        (const int*)d_in[10],           // oracle_contract_id
        (float*)d_out);
}

// round 11
// speedup vs baseline: 1.4703x; 1.1090x over previous
#include <cuda_runtime.h>
#include <math.h>
#include <cstdint>

// Problem constants (fixed by reference: B=32, T=8192, K=16)
#define BT_ROWS   (32 * 8192)
#define KDIM      16
#define ELEMS     (BT_ROWS * KDIM)       // 4194304
#define NTHR      512
#define TILE      512                    // elements per stage
#define NTILES    (ELEMS / TILE)         // 8192
#define NBLK      304                    // 152 SMs x 2 CTAs -> single wave
#define NSTAGE    4
#define EPS_F     1e-7f
#define FULLMASK  0xffffffffu

// ---- Stage layout in shared memory (bytes), TILE=512 ----
#define OFF_CID    0                     // 2 KB
#define OFF_OCID   2048
#define OFF_TRIG   4096
#define OFF_VLD    6144
#define OFF_OFIRE  8192
#define OFF_OVLD   10240
#define OFF_OCAN   12288
#define OFF_CLOG   14336                 // 6 KB
#define OFF_LIVE   20480                 // up to 2 KB
#define OFF_WSC    22528                 // 128 B (32 rows)
#define OFF_OSW    22656                 // 128 B
#define STAGE_BYTES 22784
#define SMEM_TOTAL  (NSTAGE * STAGE_BYTES)   // 91136

// Per-block partial sums: [6][NBLK]
__device__ float g_part[6 * NBLK];
__device__ unsigned int g_sem;

__device__ __forceinline__ float warp_sum_f(float v) {
#pragma unroll
    for (int o = 16; o > 0; o >>= 1) v += __shfl_down_sync(FULLMASK, v, o);
    return v;
}
__device__ __forceinline__ double warp_sum_d(double v) {
#pragma unroll
    for (int o = 16; o > 0; o >>= 1) v += __shfl_down_sync(FULLMASK, v, o);
    return v;
}

__device__ __forceinline__ void cpa16(uint32_t dst, const void* src) {
    asm volatile("cp.async.cg.shared.global [%0], [%1], 16;\n" :: "r"(dst), "l"(src));
}
__device__ __forceinline__ void cpa_commit() {
    asm volatile("cp.async.commit_group;\n" ::: "memory");
}
__device__ __forceinline__ void cpa_wait3() {
    asm volatile("cp.async.wait_group 3;\n" ::: "memory");
}

__global__ __launch_bounds__(NTHR, 2)
void lifecycle_fused(const float* __restrict__ trig,
                     const float* __restrict__ vld,
                     const float* __restrict__ clog,
                     const float* __restrict__ wsc,
                     const void*  __restrict__ live_raw,
                     const int*   __restrict__ cid,
                     const float* __restrict__ ofire,
                     const int*   __restrict__ ocan,
                     const float* __restrict__ ovld,
                     const float* __restrict__ osw,
                     const int*   __restrict__ ocid,
                     float* __restrict__ out)
{
    extern __shared__ char smem[];

    // ---- live_mask dtype sniff (same 64 words for every block; L2 broadcast) ----
    __shared__ unsigned int s_or, s_f32;
    __shared__ int s_mode;
    if (threadIdx.x == 0) { s_or = 0u; s_f32 = 0u; }
    __syncthreads();
    if (threadIdx.x < 64) {
        unsigned int x = ((const unsigned int*)live_raw)[threadIdx.x];
        unsigned int f = (x == 0x3F800000u) ? 1u : 0u;
        unsigned int a = f ? 0u : x;
#pragma unroll
        for (int o = 16; o > 0; o >>= 1) {
            a |= __shfl_down_sync(FULLMASK, a, o);
            f |= __shfl_down_sync(FULLMASK, f, o);
        }
        if ((threadIdx.x & 31) == 0) { atomicOr(&s_or, a); atomicOr(&s_f32, f); }
    }
    __syncthreads();
    if (threadIdx.x == 0) s_mode = s_f32 ? 2 : ((s_or & ~1u) ? 0 : 1);
    __syncthreads();
    const int mode = s_mode;                    // 0=u8, 1=i32, 2=f32

    const int tid = threadIdx.x;
    const int bid = blockIdx.x;
    // tiles handled by this block: bid, bid+NBLK, ... (27 or 26 of them)
    const int count = (NTILES - bid + NBLK - 1) / NBLK;

    const uint32_t sbase = (uint32_t)__cvta_generic_to_shared(smem);

    // ---- tile stage: issue cp.async for every array, one commit group ----
    auto stage_copy = [&](int j) {   // j = local tile ordinal
        const int t = bid + j * NBLK;
        const size_t eb = (size_t)t * TILE;
        const uint32_t sb = sbase + (uint32_t)(j & (NSTAGE - 1)) * STAGE_BYTES;
        if (tid < 128) {  // 7 arrays x 2KB (128 chunks each)
            cpa16(sb + OFF_CID   + tid*16, (const char*)cid   + eb*4 + tid*16);
            cpa16(sb + OFF_OCID  + tid*16, (const char*)ocid  + eb*4 + tid*16);
            cpa16(sb + OFF_TRIG  + tid*16, (const char*)trig  + eb*4 + tid*16);
            cpa16(sb + OFF_VLD   + tid*16, (const char*)vld   + eb*4 + tid*16);
            cpa16(sb + OFF_OFIRE + tid*16, (const char*)ofire + eb*4 + tid*16);
            cpa16(sb + OFF_OVLD  + tid*16, (const char*)ovld  + eb*4 + tid*16);
            cpa16(sb + OFF_OCAN  + tid*16, (const char*)ocan  + eb*4 + tid*16);
        } else {          // clog 6KB = 384 chunks, threads 128..511
            const int u = tid - 128;
            cpa16(sb + OFF_CLOG + u*16, (const char*)clog + eb*12 + u*16);
        }
        // live: 512B (32 chunks) or 2KB (128 chunks)
        if (mode == 0) {
            if (tid < 32)
                cpa16(sb + OFF_LIVE + tid*16, (const char*)live_raw + eb + tid*16);
        } else {
            if (tid < 128)
                cpa16(sb + OFF_LIVE + tid*16, (const char*)live_raw + eb*4 + tid*16);
        }
        // wsc / osw: 128B each (8 chunks)
        if (tid < 8) {
            cpa16(sb + OFF_WSC + tid*16, (const char*)wsc + (eb >> 4)*4 + tid*16);
            cpa16(sb + OFF_OSW + tid*16, (const char*)osw + (eb >> 4)*4 + tid*16);
        }
        cpa_commit();
    };

    float fire_s = 0.f, m_s = 0.f, val_s = 0.f, can_s = 0.f, has_s = 0.f, w_s = 0.f;

    const int k   = tid & 15;   // element within row
    const int row = tid >> 4;   // local row (32 rows per tile)

    // ---- prologue: fill 3 stages ----
    stage_copy(0); stage_copy(1); stage_copy(2);

#pragma unroll 1
    for (int j = 0; j < count; ++j) {
        if (j + 3 < count) stage_copy(j + 3);
        else               cpa_commit();       // keep group accounting exact
        cpa_wait3();                            // tile j complete
        __syncthreads();

        const char* sb = smem + (j & (NSTAGE - 1)) * STAGE_BYTES;

        // 16-entry row ocid table: 4 broadcast LDS.128
        int ov[16];
        {
            const int4* orow = (const int4*)(sb + OFF_OCID) + row * 4;
#pragma unroll
            for (int gq = 0; gq < 4; ++gq) {
                int4 tt = orow[gq];
                ov[4*gq+0] = tt.x; ov[4*gq+1] = tt.y; ov[4*gq+2] = tt.z; ov[4*gq+3] = tt.w;
            }
        }

        const int   c  = ((const int*)(sb + OFF_CID))[tid];
        const float th = ((const float*)(sb + OFF_TRIG))[tid];
        const float vv = ((const float*)(sb + OFF_VLD))[tid];

        bool lm;
        if (mode == 0)      lm = ((const unsigned char*)(sb + OFF_LIVE))[tid] != 0;
        else if (mode == 1) lm = ((const int*)(sb + OFF_LIVE))[tid] != 0;
        else                lm = ((const float*)(sb + OFF_LIVE))[tid] != 0.0f;

        // first-match scan: build match mask, ffs for smallest ko
        unsigned int mmask = 0u;
#pragma unroll
        for (int ko = 0; ko < 16; ++ko)
            mmask |= (ov[ko] == c) ? (1u << ko) : 0u;
        const bool fnd = (mmask != 0u) && (c != 0);
        const int  idx = fnd ? (__ffs(mmask) - 1) : 0;
        const int  gl  = row * 16 + idx;

        if (lm) {
            m_s += 1.0f;

            // oracle targets are exactly {0,1}; select-form BCE is exact
            const bool tfb = fnd && (((const float*)(sb + OFF_OFIRE))[gl] != 0.0f);
            const bool tvb = fnd && (((const float*)(sb + OFF_OVLD))[gl] != 0.0f);
            const int  ct  = fnd ? ((const int*)(sb + OFF_OCAN))[gl] : 0;

            float p = fminf(fmaxf(th, EPS_F), 1.0f - EPS_F);
            fire_s -= __logf(tfb ? p : 1.0f - p);

            float q = fminf(fmaxf(vv, EPS_F), 1.0f - EPS_F);
            val_s -= __logf(tvb ? q : 1.0f - q);

            if (ct > 0) {
                const float* lp = (const float*)(sb + OFF_CLOG) + (size_t)tid * 3;
                float x0 = lp[0], x1 = lp[1], x2 = lp[2];
                float mx = fmaxf(x0, fmaxf(x1, x2));
                float s  = __expf(x0 - mx) + __expf(x1 - mx) + __expf(x2 - mx);
                int tgt = ct - 1;
                tgt = tgt < 0 ? 0 : (tgt > 2 ? 2 : tgt);
                float xt = (tgt == 0) ? x0 : ((tgt == 1) ? x1 : x2);
                can_s += mx + __logf(s) - xt;
                has_s += 1.0f;
            }
        }

        // write-head BCE-with-logits: one per row
        if (k == 0) {
            float wx = ((const float*)(sb + OFF_WSC))[row];
            float wy = ((const float*)(sb + OFF_OSW))[row];
            w_s += fmaxf(wx, 0.0f) - wx * wy + __logf(1.0f + __expf(-fabsf(wx)));
        }

        __syncthreads();   // buffer j%4 is re-staged at iteration j+1
    }

    // ---- Deterministic block reduction of 6 float accumulators ----
    __shared__ float sm[16][6];
    {
        float vals[6] = {fire_s, m_s, val_s, can_s, has_s, w_s};
#pragma unroll
        for (int jj = 0; jj < 6; ++jj) vals[jj] = warp_sum_f(vals[jj]);
        const int wid = tid >> 5, lid = tid & 31;
        if (lid == 0) {
#pragma unroll
            for (int jj = 0; jj < 6; ++jj) sm[wid][jj] = vals[jj];
        }
        __syncthreads();
        if (wid == 0) {
#pragma unroll
            for (int jj = 0; jj < 6; ++jj) {
                float v = (lid < (NTHR / 32)) ? sm[lid][jj] : 0.0f;
                v = warp_sum_f(v);
                if (lid == 0) g_part[jj * NBLK + blockIdx.x] = v;
            }
        }
    }

    // ---- Last-block finalize ----
    __shared__ int s_last;
    if (tid == 0) {
        __threadfence();
        unsigned int t = atomicAdd(&g_sem, 1u);
        s_last = (t == NBLK - 1) ? 1 : 0;
    }
    __syncthreads();
    if (!s_last) return;

    __shared__ double smd[16];
    double tot[6];
#pragma unroll
    for (int jj = 0; jj < 6; ++jj) {
        double v = 0.0;
        for (int i = tid; i < NBLK; i += NTHR)
            v += (double)__ldcg(&g_part[jj * NBLK + i]);
        v = warp_sum_d(v);
        const int wid = tid >> 5, lid = tid & 31;
        if (lid == 0) smd[wid] = v;
        __syncthreads();
        double r = 0.0;
        if (wid == 0) {
            r = (lid < (NTHR / 32)) ? smd[lid] : 0.0;
            r = warp_sum_d(r);
        }
        tot[jj] = r;
        __syncthreads();
    }
    if (tid == 0) {
        double n     = fmax(tot[1], 1.0);
        double fire  = tot[0] / n;
        double canc  = (tot[4] > 0.0) ? tot[3] / fmax(tot[4], 1.0) : 0.0;
        double valid = 0.5 * tot[2] / n;
        double wr    = 0.5 * tot[5] / (double)BT_ROWS;
        out[0] = (float)fire;
        out[1] = (float)canc;
        out[2] = (float)valid;
        out[3] = (float)wr;
        out[4] = (float)(fire + canc + valid + wr);
        g_sem = 0;
    }
}

extern "C" void kernel_launch(void* const* d_in, const int* in_sizes, int n_in,
                              void* d_out, int out_size)
{
    (void)in_sizes; (void)n_in; (void)out_size;
    cudaFuncSetAttribute(lifecycle_fused,
                         cudaFuncAttributeMaxDynamicSharedMemorySize, SMEM_TOTAL);
    lifecycle_fused<<<NBLK, NTHR, SMEM_TOTAL>>>(
        (const float*)d_in[0],          // trigger_hazard
        (const float*)d_in[1],          // validity
        (const float*)d_in[2],          // cancel_logits
        (const float*)d_in[3],          // write_score
        d_in[4],                        // live_mask (dtype auto-detected)
        (const int*)d_in[5],            // contract_id
        (const float*)d_in[6],          // oracle_fire
        (const int*)d_in[7],            // oracle_cancel
        (const float*)d_in[8],          // oracle_valid
        (const float*)d_in[9],          // oracle_should_write
        (const int*)d_in[10],           // oracle_contract_id
        (float*)d_out);
}